// round 1
// baseline (speedup 1.0000x reference)
#include <cuda_runtime.h>
#include <cstdint>

// ---------------------------------------------------------------------------
// GAT(128->16) -> relu -> GAT(16->10) -> Linear(10->10) -> relu -> Linear(10->1)
// Softmax max-shift is dropped (mathematically identical; logits bounded ~13).
// Scatter via red.global.add.v4.f32 (sm_90+ vector reductions).
// ---------------------------------------------------------------------------

#define NMAX 100096

__device__ float g_h1 [NMAX * 16];
__device__ float g_as1[NMAX];
__device__ float g_ad1[NMAX];
__device__ float g_acc1[NMAX * 16];
__device__ float g_den1[NMAX];

__device__ float g_h2 [NMAX * 12];   // padded 10 -> 12 for float4 alignment
__device__ float g_as2[NMAX];
__device__ float g_ad2[NMAX];
__device__ float g_acc2[NMAX * 12];
__device__ float g_den2[NMAX];

__device__ int g_is64;

// --------------------------- dtype detection -------------------------------
// edge_index is declared int64 in the reference, but jax without x64 yields
// int32. If data is int64 (values < 2^31), every odd 32-bit word is 0.
__global__ void k_detect(const int* __restrict__ e32, long long n32)
{
    __shared__ int red[256];
    int t = threadIdx.x;
    int v = 0;
    long long stride = n32 / 2048; if (stride < 2) stride = 2;
    #pragma unroll
    for (int i = 0; i < 8; i++) {
        long long idx = (((long long)(t * 8 + i)) * stride) | 1LL;  // odd index
        if (idx < n32) v |= e32[idx];
    }
    red[t] = v;
    __syncthreads();
    for (int s = 128; s > 0; s >>= 1) {
        if (t < s) red[t] |= red[t + s];
        __syncthreads();
    }
    if (t == 0) g_is64 = (red[0] == 0) ? 1 : 0;
}

// --------------------------- layer-1 GEMM ----------------------------------
// h1 = x @ W1 [N,16]; asrc1 = h1 . a1_src; adst1 = h1 . a1_dst.
// Also zeroes the layer-1 accumulators (graph-replay safe).
__global__ void k_gemm1(const float* __restrict__ x, const float* __restrict__ W1,
                        const float* __restrict__ a1s, const float* __restrict__ a1d,
                        int N)
{
    __shared__ float4 Ws[128 * 4];              // W1 as 128 rows x 4 float4
    for (int i = threadIdx.x; i < 512; i += blockDim.x)
        Ws[i] = ((const float4*)W1)[i];
    __syncthreads();

    int n = blockIdx.x * blockDim.x + threadIdx.x;
    if (n >= N) return;

    float acc[16];
    #pragma unroll
    for (int c = 0; c < 16; c++) acc[c] = 0.f;

    const float4* xr = (const float4*)(x + (size_t)n * 128);
    #pragma unroll 8
    for (int kq = 0; kq < 32; kq++) {
        float4 xv = xr[kq];
        #pragma unroll
        for (int j = 0; j < 4; j++) {
            float xk = (&xv.x)[j];
            int k = kq * 4 + j;
            float4 w0 = Ws[k * 4 + 0];
            float4 w1 = Ws[k * 4 + 1];
            float4 w2 = Ws[k * 4 + 2];
            float4 w3 = Ws[k * 4 + 3];
            acc[ 0] += xk * w0.x; acc[ 1] += xk * w0.y;
            acc[ 2] += xk * w0.z; acc[ 3] += xk * w0.w;
            acc[ 4] += xk * w1.x; acc[ 5] += xk * w1.y;
            acc[ 6] += xk * w1.z; acc[ 7] += xk * w1.w;
            acc[ 8] += xk * w2.x; acc[ 9] += xk * w2.y;
            acc[10] += xk * w2.z; acc[11] += xk * w2.w;
            acc[12] += xk * w3.x; acc[13] += xk * w3.y;
            acc[14] += xk * w3.z; acc[15] += xk * w3.w;
        }
    }

    float as = 0.f, ad = 0.f;
    #pragma unroll
    for (int c = 0; c < 16; c++) { as += acc[c] * a1s[c]; ad += acc[c] * a1d[c]; }

    float4* hrow = (float4*)(g_h1  + (size_t)n * 16);
    float4* arow = (float4*)(g_acc1 + (size_t)n * 16);
    #pragma unroll
    for (int q = 0; q < 4; q++) {
        hrow[q] = make_float4(acc[q*4], acc[q*4+1], acc[q*4+2], acc[q*4+3]);
        arow[q] = make_float4(0.f, 0.f, 0.f, 0.f);
    }
    g_as1[n] = as; g_ad1[n] = ad; g_den1[n] = 0.f;
}

// --------------------------- edge scatter ----------------------------------
// One thread per edge (t < E) or per self-loop (t >= E).
// w = exp(leakyrelu(asrc[s] + adst[d])); den[d] += w; acc[d] += w * h[s].
template<int C4, int L>
__global__ void k_edge(const void* __restrict__ eiv, long long E, int N)
{
    long long t = (long long)blockIdx.x * blockDim.x + threadIdx.x;
    if (t >= E + N) return;

    int s, d;
    if (t < E) {
        if (g_is64) {
            const long long* ei = (const long long*)eiv;
            s = (int)ei[t];
            d = (int)ei[E + t];
        } else {
            const int* ei = (const int*)eiv;
            s = ei[t];
            d = ei[E + t];
        }
    } else {
        s = d = (int)(t - E);
    }

    const float* as  = (L == 1) ? g_as1  : g_as2;
    const float* ad  = (L == 1) ? g_ad1  : g_ad2;
    const float* h   = (L == 1) ? g_h1   : g_h2;
    float*       acc = (L == 1) ? g_acc1 : g_acc2;
    float*       den = (L == 1) ? g_den1 : g_den2;

    float e = as[s] + ad[d];
    e = (e > 0.f) ? e : 0.2f * e;
    float w = __expf(e);

    atomicAdd(den + d, w);

    const float4* hs   = (const float4*)(h + (size_t)s * (C4 * 4));
    float*        outp = acc + (size_t)d * (C4 * 4);
    #pragma unroll
    for (int q = 0; q < C4; q++) {
        float4 v = hs[q];
        asm volatile("red.global.add.v4.f32 [%0], {%1,%2,%3,%4};"
                     :: "l"(outp + q * 4),
                        "f"(v.x * w), "f"(v.y * w), "f"(v.z * w), "f"(v.w * w)
                     : "memory");
    }
}

// --------------------------- between-layer ---------------------------------
// z = relu(acc1/den1 + b1); h2 = z @ W2; asrc2/adst2; zero layer-2 accums.
__global__ void k_mid(const float* __restrict__ b1, const float* __restrict__ W2,
                      const float* __restrict__ a2s, const float* __restrict__ a2d,
                      int N)
{
    int n = blockIdx.x * blockDim.x + threadIdx.x;
    if (n >= N) return;

    float inv = 1.f / g_den1[n];
    float z[16];
    #pragma unroll
    for (int c = 0; c < 16; c++) {
        float v = g_acc1[(size_t)n * 16 + c] * inv + b1[c];
        z[c] = (v > 0.f) ? v : 0.f;
    }

    float h2[10];
    #pragma unroll
    for (int j = 0; j < 10; j++) {
        float a = 0.f;
        #pragma unroll
        for (int c = 0; c < 16; c++) a += z[c] * W2[c * 10 + j];
        h2[j] = a;
    }

    float as = 0.f, ad = 0.f;
    #pragma unroll
    for (int j = 0; j < 10; j++) { as += h2[j] * a2s[j]; ad += h2[j] * a2d[j]; }

    float* hrow = g_h2  + (size_t)n * 12;
    float* arow = g_acc2 + (size_t)n * 12;
    #pragma unroll
    for (int j = 0; j < 10; j++) { hrow[j] = h2[j]; arow[j] = 0.f; }
    hrow[10] = 0.f; hrow[11] = 0.f;
    arow[10] = 0.f; arow[11] = 0.f;
    g_as2[n] = as; g_ad2[n] = ad; g_den2[n] = 0.f;
}

// --------------------------- final head ------------------------------------
// o = acc2/den2 + b2; t = relu(o @ Wl1 + bl1); y = t @ Wl2 + bl2.
__global__ void k_final(const float* __restrict__ b2, const float* __restrict__ Wl1,
                        const float* __restrict__ bl1, const float* __restrict__ Wl2,
                        const float* __restrict__ bl2, float* __restrict__ out, int N)
{
    int n = blockIdx.x * blockDim.x + threadIdx.x;
    if (n >= N) return;

    float inv = 1.f / g_den2[n];
    float o[10];
    #pragma unroll
    for (int j = 0; j < 10; j++)
        o[j] = g_acc2[(size_t)n * 12 + j] * inv + b2[j];

    float y = bl2[0];
    #pragma unroll
    for (int j = 0; j < 10; j++) {
        float tt = bl1[j];
        #pragma unroll
        for (int k = 0; k < 10; k++) tt += o[k] * Wl1[k * 10 + j];
        tt = (tt > 0.f) ? tt : 0.f;
        y += tt * Wl2[j];
    }
    out[n] = y;
}

// ---------------------------------------------------------------------------
extern "C" void kernel_launch(void* const* d_in, const int* in_sizes, int n_in,
                              void* d_out, int out_size)
{
    const float* x   = (const float*)d_in[0];
    const void*  ei  = d_in[1];
    const float* W1  = (const float*)d_in[2];
    const float* a1s = (const float*)d_in[3];
    const float* a1d = (const float*)d_in[4];
    const float* b1  = (const float*)d_in[5];
    const float* W2  = (const float*)d_in[6];
    const float* a2s = (const float*)d_in[7];
    const float* a2d = (const float*)d_in[8];
    const float* b2  = (const float*)d_in[9];
    const float* Wl1 = (const float*)d_in[10];
    const float* bl1 = (const float*)d_in[11];
    const float* Wl2 = (const float*)d_in[12];
    const float* bl2 = (const float*)d_in[13];
    float* out = (float*)d_out;

    int       N = in_sizes[0] / 128;       // 100000
    long long E = in_sizes[1] / 2;         // 3200000

    // dtype sniff (int32 slots lower bound = element count)
    k_detect<<<1, 256>>>((const int*)ei, (long long)in_sizes[1]);

    k_gemm1<<<(N + 127) / 128, 128>>>(x, W1, a1s, a1d, N);

    long long work = E + N;
    int ngrid = (int)((work + 255) / 256);
    k_edge<4, 1><<<ngrid, 256>>>(ei, E, N);

    k_mid<<<(N + 255) / 256, 256>>>(b1, W2, a2s, a2d, N);

    k_edge<3, 2><<<ngrid, 256>>>(ei, E, N);

    k_final<<<(N + 255) / 256, 256>>>(b2, Wl1, bl1, Wl2, bl2, out, N);
}

// round 2
// speedup vs baseline: 1.0961x; 1.0961x over previous
#include <cuda_runtime.h>
#include <cstdint>

// ---------------------------------------------------------------------------
// GAT(128->16) -> relu -> GAT(16->10) -> Linear(10->10) -> relu -> Linear(10->1)
// Softmax max-shift dropped (mathematically identical; logits bounded ~13).
// Scatter via red.global.add.v4.f32. Layer-2 rows padded to 16 floats with
// den folded into col 10 (3 RED messages/edge instead of 4).
// ---------------------------------------------------------------------------

#define NMAX 100096

__device__ float g_h1 [NMAX * 16];
__device__ float g_as1[NMAX];
__device__ float g_ad1[NMAX];
__device__ float g_acc1[NMAX * 16];
__device__ float g_den1[NMAX];

__device__ float g_h2 [NMAX * 16];   // cols 0..9 = h2, 10..15 = 0
__device__ float g_as2[NMAX];
__device__ float g_ad2[NMAX];
__device__ float g_acc2[NMAX * 16];  // cols 0..9 = acc, 10 = den, 11..15 = 0

__device__ int g_is64;

// --------------------------- dtype detection -------------------------------
// edge_index declared int64 in the reference, but jax w/o x64 yields int32.
// If data is int64 (values < 2^31), every odd 32-bit word is 0.
__global__ void k_detect(const int* __restrict__ e32, long long n32)
{
    __shared__ int red[256];
    int t = threadIdx.x;
    int v = 0;
    long long stride = n32 / 2048; if (stride < 2) stride = 2;
    #pragma unroll
    for (int i = 0; i < 8; i++) {
        long long idx = (((long long)(t * 8 + i)) * stride) | 1LL;  // odd index
        if (idx < n32) v |= e32[idx];
    }
    red[t] = v;
    __syncthreads();
    for (int s = 128; s > 0; s >>= 1) {
        if (t < s) red[t] |= red[t + s];
        __syncthreads();
    }
    if (t == 0) g_is64 = (red[0] == 0) ? 1 : 0;
}

// --------------------------- layer-1 GEMM ----------------------------------
__global__ void k_gemm1(const float* __restrict__ x, const float* __restrict__ W1,
                        const float* __restrict__ a1s, const float* __restrict__ a1d,
                        int N)
{
    __shared__ float4 Ws[128 * 4];              // W1 as 128 rows x 4 float4
    for (int i = threadIdx.x; i < 512; i += blockDim.x)
        Ws[i] = ((const float4*)W1)[i];
    __syncthreads();

    int n = blockIdx.x * blockDim.x + threadIdx.x;
    if (n >= N) return;

    float acc[16];
    #pragma unroll
    for (int c = 0; c < 16; c++) acc[c] = 0.f;

    const float4* xr = (const float4*)(x + (size_t)n * 128);
    #pragma unroll 8
    for (int kq = 0; kq < 32; kq++) {
        float4 xv = xr[kq];
        #pragma unroll
        for (int j = 0; j < 4; j++) {
            float xk = (&xv.x)[j];
            int k = kq * 4 + j;
            float4 w0 = Ws[k * 4 + 0];
            float4 w1 = Ws[k * 4 + 1];
            float4 w2 = Ws[k * 4 + 2];
            float4 w3 = Ws[k * 4 + 3];
            acc[ 0] += xk * w0.x; acc[ 1] += xk * w0.y;
            acc[ 2] += xk * w0.z; acc[ 3] += xk * w0.w;
            acc[ 4] += xk * w1.x; acc[ 5] += xk * w1.y;
            acc[ 6] += xk * w1.z; acc[ 7] += xk * w1.w;
            acc[ 8] += xk * w2.x; acc[ 9] += xk * w2.y;
            acc[10] += xk * w2.z; acc[11] += xk * w2.w;
            acc[12] += xk * w3.x; acc[13] += xk * w3.y;
            acc[14] += xk * w3.z; acc[15] += xk * w3.w;
        }
    }

    float as = 0.f, ad = 0.f;
    #pragma unroll
    for (int c = 0; c < 16; c++) { as += acc[c] * a1s[c]; ad += acc[c] * a1d[c]; }

    float4* hrow = (float4*)(g_h1  + (size_t)n * 16);
    float4* arow = (float4*)(g_acc1 + (size_t)n * 16);
    float4 z4 = make_float4(0.f, 0.f, 0.f, 0.f);
    #pragma unroll
    for (int q = 0; q < 4; q++) {
        hrow[q] = make_float4(acc[q*4], acc[q*4+1], acc[q*4+2], acc[q*4+3]);
        arow[q] = z4;
    }
    g_as1[n] = as; g_ad1[n] = ad; g_den1[n] = 0.f;
}

// --------------------------- edge scatter, layer 1 -------------------------
// acc1: 16 cols (4 x v4 RED) + separate scalar den RED.
__global__ void k_edge1(const void* __restrict__ eiv, long long E, int N)
{
    long long t = (long long)blockIdx.x * blockDim.x + threadIdx.x;
    if (t >= E + N) return;

    int is64 = g_is64;
    int s, d;
    if (t < E) {
        if (is64) {
            const long long* ei = (const long long*)eiv;
            s = (int)ei[t];
            d = (int)ei[E + t];
        } else {
            const int* ei = (const int*)eiv;
            s = ei[t];
            d = ei[E + t];
        }
    } else {
        s = d = (int)(t - E);
    }

    float e = g_as1[s] + g_ad1[d];
    e = (e > 0.f) ? e : 0.2f * e;
    float w = __expf(e);

    atomicAdd(g_den1 + d, w);

    const float4* hs   = (const float4*)(g_h1 + (size_t)s * 16);
    float*        outp = g_acc1 + (size_t)d * 16;
    #pragma unroll
    for (int q = 0; q < 4; q++) {
        float4 v = hs[q];
        asm volatile("red.global.add.v4.f32 [%0], {%1,%2,%3,%4};"
                     :: "l"(outp + q * 4),
                        "f"(v.x * w), "f"(v.y * w), "f"(v.z * w), "f"(v.w * w)
                     : "memory");
    }
}

// --------------------------- edge scatter, layer 2 -------------------------
// acc2: 16-col rows, den folded at col 10 -> exactly 3 v4 RED messages.
__global__ void k_edge2(const void* __restrict__ eiv, long long E, int N)
{
    long long t = (long long)blockIdx.x * blockDim.x + threadIdx.x;
    if (t >= E + N) return;

    int is64 = g_is64;
    int s, d;
    if (t < E) {
        if (is64) {
            const long long* ei = (const long long*)eiv;
            s = (int)ei[t];
            d = (int)ei[E + t];
        } else {
            const int* ei = (const int*)eiv;
            s = ei[t];
            d = ei[E + t];
        }
    } else {
        s = d = (int)(t - E);
    }

    float e = g_as2[s] + g_ad2[d];
    e = (e > 0.f) ? e : 0.2f * e;
    float w = __expf(e);

    const float4* hs   = (const float4*)(g_h2 + (size_t)s * 16);
    float*        outp = g_acc2 + (size_t)d * 16;
    float4 v0 = hs[0];
    float4 v1 = hs[1];
    float4 v2 = hs[2];                       // {h8, h9, 0, 0}
    asm volatile("red.global.add.v4.f32 [%0], {%1,%2,%3,%4};"
                 :: "l"(outp + 0),
                    "f"(v0.x * w), "f"(v0.y * w), "f"(v0.z * w), "f"(v0.w * w)
                 : "memory");
    asm volatile("red.global.add.v4.f32 [%0], {%1,%2,%3,%4};"
                 :: "l"(outp + 4),
                    "f"(v1.x * w), "f"(v1.y * w), "f"(v1.z * w), "f"(v1.w * w)
                 : "memory");
    asm volatile("red.global.add.v4.f32 [%0], {%1,%2,%3,%4};"
                 :: "l"(outp + 8),
                    "f"(v2.x * w), "f"(v2.y * w), "f"(w), "f"(0.f)
                 : "memory");
}

// --------------------------- between-layer ---------------------------------
// z = relu(acc1/den1 + b1); h2 = z @ W2; asrc2/adst2; zero layer-2 accums.
// All small tensors staged in shared memory; all global IO is float4.
__global__ void k_mid(const float* __restrict__ b1, const float* __restrict__ W2,
                      const float* __restrict__ a2s, const float* __restrict__ a2d,
                      int N)
{
    __shared__ float sW2[160], sb1[16], sas[10], sad[10];
    int tx = threadIdx.x;
    if (tx < 160) sW2[tx] = W2[tx];
    if (tx >= 160 && tx < 176) sb1[tx - 160] = b1[tx - 160];
    if (tx >= 176 && tx < 186) sas[tx - 176] = a2s[tx - 176];
    if (tx >= 186 && tx < 196) sad[tx - 186] = a2d[tx - 186];
    __syncthreads();

    int n = blockIdx.x * blockDim.x + tx;
    if (n >= N) return;

    // batched independent loads (MLP=5)
    float den = g_den1[n];
    const float4* ar = (const float4*)(g_acc1 + (size_t)n * 16);
    float4 a0 = ar[0], a1 = ar[1], a2 = ar[2], a3 = ar[3];
    float inv = 1.f / den;

    float z[16];
    float* av = &a0.x;
    #pragma unroll
    for (int q = 0; q < 4; q++) {
        float4 aq = (q == 0) ? a0 : (q == 1) ? a1 : (q == 2) ? a2 : a3;
        #pragma unroll
        for (int j = 0; j < 4; j++) {
            float v = (&aq.x)[j] * inv + sb1[q * 4 + j];
            z[q * 4 + j] = (v > 0.f) ? v : 0.f;
        }
    }
    (void)av;

    float h2[10];
    #pragma unroll
    for (int j = 0; j < 10; j++) h2[j] = 0.f;
    #pragma unroll
    for (int c = 0; c < 16; c++) {
        float zc = z[c];
        #pragma unroll
        for (int j = 0; j < 10; j++) h2[j] += zc * sW2[c * 10 + j];
    }

    float as = 0.f, ad = 0.f;
    #pragma unroll
    for (int j = 0; j < 10; j++) { as += h2[j] * sas[j]; ad += h2[j] * sad[j]; }

    float4* hrow = (float4*)(g_h2  + (size_t)n * 16);
    float4* arow = (float4*)(g_acc2 + (size_t)n * 16);
    float4 z4 = make_float4(0.f, 0.f, 0.f, 0.f);
    hrow[0] = make_float4(h2[0], h2[1], h2[2], h2[3]);
    hrow[1] = make_float4(h2[4], h2[5], h2[6], h2[7]);
    hrow[2] = make_float4(h2[8], h2[9], 0.f, 0.f);
    hrow[3] = z4;
    arow[0] = z4; arow[1] = z4; arow[2] = z4; arow[3] = z4;
    g_as2[n] = as; g_ad2[n] = ad;
}

// --------------------------- final head ------------------------------------
// o = acc2/den2 + b2; t = relu(o @ Wl1 + bl1); y = t @ Wl2 + bl2.
__global__ void k_final(const float* __restrict__ b2, const float* __restrict__ Wl1,
                        const float* __restrict__ bl1, const float* __restrict__ Wl2,
                        const float* __restrict__ bl2, float* __restrict__ out, int N)
{
    __shared__ float sW[100], sb2[10], sbl1[10], sWl2[10], sbl2;
    int tx = threadIdx.x;
    if (tx < 100) sW[tx] = Wl1[tx];
    if (tx >= 100 && tx < 110) sb2[tx - 100] = b2[tx - 100];
    if (tx >= 110 && tx < 120) sbl1[tx - 110] = bl1[tx - 110];
    if (tx >= 120 && tx < 130) sWl2[tx - 120] = Wl2[tx - 120];
    if (tx == 130) sbl2 = bl2[0];
    __syncthreads();

    int n = blockIdx.x * blockDim.x + tx;
    if (n >= N) return;

    const float4* ar = (const float4*)(g_acc2 + (size_t)n * 16);
    float4 a0 = ar[0], a1 = ar[1], a2 = ar[2];
    float inv = 1.f / a2.z;                          // den at col 10

    float o[10];
    o[0] = a0.x * inv + sb2[0]; o[1] = a0.y * inv + sb2[1];
    o[2] = a0.z * inv + sb2[2]; o[3] = a0.w * inv + sb2[3];
    o[4] = a1.x * inv + sb2[4]; o[5] = a1.y * inv + sb2[5];
    o[6] = a1.z * inv + sb2[6]; o[7] = a1.w * inv + sb2[7];
    o[8] = a2.x * inv + sb2[8]; o[9] = a2.y * inv + sb2[9];

    float y = sbl2;
    #pragma unroll
    for (int j = 0; j < 10; j++) {
        float tt = sbl1[j];
        #pragma unroll
        for (int k = 0; k < 10; k++) tt += o[k] * sW[k * 10 + j];
        tt = (tt > 0.f) ? tt : 0.f;
        y += tt * sWl2[j];
    }
    out[n] = y;
}

// ---------------------------------------------------------------------------
extern "C" void kernel_launch(void* const* d_in, const int* in_sizes, int n_in,
                              void* d_out, int out_size)
{
    const float* x   = (const float*)d_in[0];
    const void*  ei  = d_in[1];
    const float* W1  = (const float*)d_in[2];
    const float* a1s = (const float*)d_in[3];
    const float* a1d = (const float*)d_in[4];
    const float* b1  = (const float*)d_in[5];
    const float* W2  = (const float*)d_in[6];
    const float* a2s = (const float*)d_in[7];
    const float* a2d = (const float*)d_in[8];
    const float* b2  = (const float*)d_in[9];
    const float* Wl1 = (const float*)d_in[10];
    const float* bl1 = (const float*)d_in[11];
    const float* Wl2 = (const float*)d_in[12];
    const float* bl2 = (const float*)d_in[13];
    float* out = (float*)d_out;

    int       N = in_sizes[0] / 128;       // 100000
    long long E = in_sizes[1] / 2;         // 3200000

    k_detect<<<1, 256>>>((const int*)ei, (long long)in_sizes[1]);

    k_gemm1<<<(N + 127) / 128, 128>>>(x, W1, a1s, a1d, N);

    long long work = E + N;
    int ngrid = (int)((work + 255) / 256);
    k_edge1<<<ngrid, 256>>>(ei, E, N);

    k_mid<<<(N + 255) / 256, 256>>>(b1, W2, a2s, a2d, N);

    k_edge2<<<ngrid, 256>>>(ei, E, N);

    k_final<<<(N + 255) / 256, 256>>>(b2, Wl1, bl1, Wl2, bl2, out, N);
}